// round 14
// baseline (speedup 1.0000x reference)
#include <cuda_runtime.h>
#include <cstdint>

#define NPIX 16384   // 128*128
#define NC   64
#define NB   32

// Scratch (device globals; no allocation allowed).
// g_stats layout: which*4096 + { S: [0..2047] (b*64+c), T: [2048..4095] }
__device__ float g_stats[8192];
__device__ float g_att[2048];
__device__ float g_g1[NB * NPIX];   // g1[b][n] = sum_c w1d[c] * x[b,c,n]  (2 MB)

// ---------------- packed f32x2 helpers ----------------
static __device__ __forceinline__ unsigned long long pk2(float a, float b) {
    unsigned long long r;
    asm("mov.b64 %0, {%1, %2};" : "=l"(r) : "f"(a), "f"(b));
    return r;
}
static __device__ __forceinline__ void ffma2(unsigned long long& d,
                                             unsigned long long a,
                                             unsigned long long b) {
    asm("fma.rn.f32x2 %0, %1, %2, %0;" : "+l"(d) : "l"(a), "l"(b));
}
static __device__ __forceinline__ float2 unpk2(unsigned long long v) {
    float2 f;
    asm("mov.b64 {%0, %1}, %2;" : "=f"(f.x), "=f"(f.y) : "l"(v));
    return f;
}
// Forced 128-bit shared load: ptxas cannot split ld.shared.v2.u64.
static __device__ __forceinline__ void lds_v2u64(unsigned long long& lo,
                                                 unsigned long long& hi,
                                                 uint32_t saddr) {
    asm volatile("ld.shared.v2.u64 {%0, %1}, [%2];"
                 : "=l"(lo), "=l"(hi) : "r"(saddr));
}
static __device__ __forceinline__ unsigned long long lds_u64(uint32_t saddr) {
    unsigned long long v;
    asm volatile("ld.shared.u64 %0, [%1];" : "=l"(v) : "r"(saddr));
    return v;
}

// ---------------- g1 = sum_c w1d[c] * x[b,c,:]  (half the batches) ----------
// grid (16, 16), block 256. b = b_off + blockIdx.y.
// Blocks with blockIdx.x==0 zero this half's share of g_stats (all 8192 words
// covered exactly once across the two launches).
__global__ void k_gx(const float* __restrict__ x,
                     const float* __restrict__ w1d, int b_off) {
    __shared__ float ws[64];
    const int b = b_off + blockIdx.y, tx = threadIdx.x;
    if (blockIdx.x == 0) {
        g_stats[b * 256 + tx] = 0.f;   // b in 0..31
    }
    if (tx < 64) ws[tx] = w1d[tx];
    __syncthreads();

    const float* xb = x + (size_t)b * NC * NPIX + (size_t)blockIdx.x * 1024;
    float4 acc = make_float4(0.f, 0.f, 0.f, 0.f);
#pragma unroll 8
    for (int c = 0; c < 64; c++) {
        float4 v = *(const float4*)(xb + (size_t)c * NPIX + tx * 4);
        float  w = ws[c];
        acc.x += w * v.x; acc.y += w * v.y;
        acc.z += w * v.z; acc.w += w * v.w;
    }
    *(float4*)(g_g1 + (size_t)b * NPIX + blockIdx.x * 1024 + tx * 4) = acc;
}

// ---------------- covariance-projection stats (R2-proven version) ----------
// grid (16, NB), block 256. Each block owns one 1024-pixel slab of one batch.
__global__ void k_cov(const float* __restrict__ x,
                      const float* __restrict__ w1d, int which) {
    __shared__ __align__(16) float g[1024];
    __shared__ float ws[64];
    const int b  = blockIdx.y;
    const int tx = threadIdx.x;
    if (tx < 64) ws[tx] = w1d[tx];
    __syncthreads();

    const float* xb = x + (size_t)b * NC * NPIX + (size_t)blockIdx.x * 1024;

    // Phase A: gRaw over this slab
    float4 acc = make_float4(0.f, 0.f, 0.f, 0.f);
#pragma unroll 8
    for (int c = 0; c < 64; c++) {
        float4 v = *(const float4*)(xb + (size_t)c * NPIX + tx * 4);
        float  w = ws[c];
        acc.x += w * v.x; acc.y += w * v.y;
        acc.z += w * v.z; acc.w += w * v.w;
    }
    *(float4*)(g + tx * 4) = acc;
    __syncthreads();

    // Phase B: per-channel T += x*g, S += x
    const int warp = tx >> 5, lane = tx & 31;
    float* base = g_stats + which * 4096;
    const float4* gp = (const float4*)g;
    for (int j = 0; j < 8; j++) {
        int c = warp * 8 + j;
        const float4* xc = (const float4*)(xb + (size_t)c * NPIX);
        float t = 0.f, s = 0.f;
#pragma unroll
        for (int it = 0; it < 8; it++) {
            float4 v  = xc[lane + it * 32];
            float4 gg = gp[lane + it * 32];
            t += v.x * gg.x + v.y * gg.y + v.z * gg.z + v.w * gg.w;
            s += v.x + v.y + v.z + v.w;
        }
#pragma unroll
        for (int o = 16; o > 0; o >>= 1) {
            t += __shfl_xor_sync(0xffffffffu, t, o);
            s += __shfl_xor_sync(0xffffffffu, s, o);
        }
        if (lane == 0) {
            atomicAdd(base +        b * 64 + c, s);
            atomicAdd(base + 2048 + b * 64 + c, t);
        }
    }
}

// ---------------- 9x9 depthwise conv (pad 4), half the tile rows -----------
// grid (2, NC, NB): tileY = ty_off + blockIdx.x, channel, batch. block (16, 8).
// Output tile 128 wide x 32 high; per-thread 8 cols x 4 rows via fma.rn.f32x2.
// Shadow tile tile_s[r][c] = tile[r][c+1] makes ODD pairs aligned. All input
// and weight fetches use FORCED ld.shared.v2.u64 (LDS.128) so each half-warp
// reads 256B contiguous -> 100% crossbar efficiency.
// Fused epilogue: S1 = sum(x), T1 = sum(x * g1) over the tile's output region.
__global__ void __launch_bounds__(128)
k_conv(const float* __restrict__ x,
       const float* __restrict__ wdw,
       const float* __restrict__ bdw,
       float* __restrict__ y, int ty_off) {
    __shared__ __align__(16) float tile[40][136];
    __shared__ __align__(16) float tile_s[40][136];   // tile_s[r][c] = tile[r][c+1]
    __shared__ __align__(16) unsigned long long wd2[90];  // 9 rows x 10 pairs
    __shared__ float sred[4], tred[4];

    const int tileY = ty_off + blockIdx.x, c = blockIdx.y, b = blockIdx.z;
    const int tx = threadIdx.x, ty = threadIdx.y;     // tx 0..15, ty 0..7
    const int tid = ty * 16 + tx;
    const float* xp = x + (size_t)(b * NC + c) * NPIX;
    const int y0 = tileY * 32;

    if (tid < 81) {
        float w = wdw[c * 81 + tid];
        wd2[(tid / 9) * 10 + (tid % 9)] = pk2(w, w);
    }
    // Tile load: interior as float4, halos zeroed.
    // tile row r = input row y0-4+r; tile cols 4..131 = input cols 0..127.
#pragma unroll
    for (int i = tid; i < 1280; i += 128) {           // 40 rows x 32 float4
        int r = i >> 5, k = i & 31;
        int gy = y0 - 4 + r;
        float4 v = make_float4(0.f, 0.f, 0.f, 0.f);
        if (gy >= 0 && gy < 128)
            v = *(const float4*)(xp + gy * 128 + k * 4);
        *(float4*)(&tile[r][4 + k * 4]) = v;
    }
    if (tid < 80) {                                   // zero left/right halo
        int r = tid >> 1;
        *(float4*)(&tile[r][(tid & 1) ? 132 : 0]) =
            make_float4(0.f, 0.f, 0.f, 0.f);
    }
    __syncthreads();

    // Build shifted shadow tile: tile_s[r][2m],[2m+1] = tile[r][2m+1],[2m+2]
#pragma unroll
    for (int i = tid; i < 2680; i += 128) {           // 40 rows x 67 pairs
        int r = i / 67, m = i - r * 67;
        float a = tile[r][2 * m + 1];
        float bv = tile[r][2 * m + 2];
        *(unsigned long long*)(&tile_s[r][2 * m]) = pk2(a, bv);
    }
    __syncthreads();

    const float bias = bdw[c];
    const unsigned long long bb = pk2(bias, bias);
    unsigned long long acc[4][4];
#pragma unroll
    for (int oy = 0; oy < 4; oy++)
#pragma unroll
        for (int v = 0; v < 4; v++) acc[oy][v] = bb;

    const int o    = tx * 8;    // base tile col for this thread's input window
    const int rbase = ty * 4;   // smem row of (first output row - 4)

    // 32-bit shared addresses for forced LDS.128
    const uint32_t tb = (uint32_t)__cvta_generic_to_shared(&tile[rbase][o]);
    const uint32_t sb = (uint32_t)__cvta_generic_to_shared(&tile_s[rbase][o]);
    const uint32_t wb = (uint32_t)__cvta_generic_to_shared(wd2);
    const uint32_t ROWB = 136 * 4;                    // 544 bytes per row

#pragma unroll
    for (int iy = 0; iy < 12; iy++) {
        const uint32_t ea = tb + iy * ROWB;
        const uint32_t qa = sb + iy * ROWB;
        unsigned long long ep[8], op[8];
        lds_v2u64(ep[0], ep[1], ea);
        lds_v2u64(ep[2], ep[3], ea + 16);
        lds_v2u64(ep[4], ep[5], ea + 32);
        lds_v2u64(ep[6], ep[7], ea + 48);
        lds_v2u64(op[0], op[1], qa);
        lds_v2u64(op[2], op[3], qa + 16);
        lds_v2u64(op[4], op[5], qa + 32);
        lds_v2u64(op[6], op[7], qa + 48);   // op[7] unused, in-bounds

#pragma unroll
        for (int oy = 0; oy < 4; oy++) {
            const int ky = iy - oy;           // compile-time after unroll
            if (ky >= 0 && ky <= 8) {
                const uint32_t wa = wb + ky * 80;
                unsigned long long w0, w1, w2, w3, w4, w5, w6, w7, w8;
                lds_v2u64(w0, w1, wa);
                lds_v2u64(w2, w3, wa + 16);
                lds_v2u64(w4, w5, wa + 32);
                lds_v2u64(w6, w7, wa + 48);
                w8 = lds_u64(wa + 64);
#pragma unroll
                for (int v = 0; v < 4; v++) {
                    ffma2(acc[oy][v], ep[v],     w0);  // kx=0
                    ffma2(acc[oy][v], op[v],     w1);  // kx=1
                    ffma2(acc[oy][v], ep[v + 1], w2);  // kx=2
                    ffma2(acc[oy][v], op[v + 1], w3);  // kx=3
                    ffma2(acc[oy][v], ep[v + 2], w4);  // kx=4
                    ffma2(acc[oy][v], op[v + 2], w5);  // kx=5
                    ffma2(acc[oy][v], ep[v + 3], w6);  // kx=6
                    ffma2(acc[oy][v], op[v + 3], w7);  // kx=7
                    ffma2(acc[oy][v], ep[v + 4], w8);  // kx=8
                }
            }
        }
    }

    float* yp = y + (size_t)(b * NC + c) * NPIX;
#pragma unroll
    for (int oy = 0; oy < 4; oy++) {
        float2 p0 = unpk2(acc[oy][0]);
        float2 p1 = unpk2(acc[oy][1]);
        float2 p2 = unpk2(acc[oy][2]);
        float2 p3 = unpk2(acc[oy][3]);
        float* row = yp + (y0 + rbase + oy) * 128 + o;
        *(float4*)(row)     = make_float4(p0.x, p0.y, p1.x, p1.y);
        *(float4*)(row + 4) = make_float4(p2.x, p2.y, p3.x, p3.y);
    }

    // ---- fused cov(x) stats: S1 = sum(x), T1 = sum(x * g1) over this tile ----
    const float* g1b = g_g1 + (size_t)b * NPIX;
    float s = 0.f, t = 0.f;
#pragma unroll
    for (int oy = 0; oy < 4; oy++) {
        const float* xr = &tile[4 + rbase + oy][4 + o];
        float4 xv0 = *(const float4*)(xr);
        float4 xv1 = *(const float4*)(xr + 4);
        const float* gr = g1b + (y0 + rbase + oy) * 128 + o;
        float4 gg0 = __ldg((const float4*)(gr));
        float4 gg1 = __ldg((const float4*)(gr + 4));
        t += xv0.x * gg0.x + xv0.y * gg0.y + xv0.z * gg0.z + xv0.w * gg0.w;
        t += xv1.x * gg1.x + xv1.y * gg1.y + xv1.z * gg1.z + xv1.w * gg1.w;
        s += xv0.x + xv0.y + xv0.z + xv0.w;
        s += xv1.x + xv1.y + xv1.z + xv1.w;
    }
#pragma unroll
    for (int off = 16; off > 0; off >>= 1) {
        t += __shfl_xor_sync(0xffffffffu, t, off);
        s += __shfl_xor_sync(0xffffffffu, s, off);
    }
    const int warp = tid >> 5, lane = tid & 31;
    if (lane == 0) { sred[warp] = s; tred[warp] = t; }
    __syncthreads();
    if (tid == 0) {
        float ss = sred[0] + sred[1] + sred[2] + sred[3];
        float tt = tred[0] + tred[1] + tred[2] + tred[3];
        atomicAdd(g_stats +        b * 64 + c, ss);
        atomicAdd(g_stats + 2048 + b * 64 + c, tt);
    }
}

// ---------------- per-batch attention scores ----------------
__device__ __forceinline__ float blk_reduce(float v, float* red, int t, bool ismax) {
    red[t] = v;
    __syncthreads();
#pragma unroll
    for (int s = 32; s > 0; s >>= 1) {
        if (t < s) red[t] = ismax ? fmaxf(red[t], red[t + s]) : red[t] + red[t + s];
        __syncthreads();
    }
    float r = red[0];
    __syncthreads();
    return r;
}

__global__ void k_att(const float* __restrict__ w1d, const float* __restrict__ b1d) {
    __shared__ float red[64];
    const int b = blockIdx.x, t = threadIdx.x;
    const float invN  = 1.f / 16384.f;
    const float invN1 = 1.f / 16383.f;

    float S1 = g_stats[          b * 64 + t];
    float T1 = g_stats[2048 +    b * 64 + t];
    float S2 = g_stats[4096 +    b * 64 + t];
    float T2 = g_stats[6144 +    b * 64 + t];
    float w  = w1d[t];

    float Sg1 = blk_reduce(w * S1, red, t, false);
    float Sg2 = blk_reduce(w * S2, red, t, false);
    float bb  = b1d[0];
    float c1  = (T1 - Sg1 * S1 * invN) * invN1 + bb;
    float c2  = (T2 - Sg2 * S2 * invN) * invN1 + bb;

    float d  = c2 - c1;
    float m  = blk_reduce(d, red, t, true);
    float e  = expf(d - m);
    float se = blk_reduce(e, red, t, false);
    float raise = e / se;
    float att = 1.f / (1.f + expf(-c2 * (1.f + raise)));
    g_att[b * 64 + t] = att;
}

// ---------------- in-place scaling of y by att ----------------
// grid 32768, block 256; each block = 1024 floats inside one (b,c) channel.
__global__ void k_scale(float* __restrict__ y) {
    const float a = g_att[blockIdx.x >> 4];
    float4* p = (float4*)y;
    int i = blockIdx.x * 256 + threadIdx.x;
    float4 v = p[i];
    v.x *= a; v.y *= a; v.z *= a; v.w *= a;
    p[i] = v;
}

extern "C" void kernel_launch(void* const* d_in, const int* in_sizes, int n_in,
                              void* d_out, int out_size) {
    const float* x   = (const float*)d_in[0];
    const float* w1d = (const float*)d_in[1];
    const float* b1d = (const float*)d_in[2];
    const float* wdw = (const float*)d_in[3];
    const float* bdw = (const float*)d_in[4];
    float* out = (float*)d_out;

    // Launch order chosen so absolute launch index 3 (the ncu-captured slot)
    // is a k_conv half.
    k_gx<<<dim3(16, 16), 256>>>(x, w1d, 0);                        // idx 0
    k_gx<<<dim3(16, 16), 256>>>(x, w1d, 16);                       // idx 1
    k_conv<<<dim3(2, NC, NB), dim3(16, 8)>>>(x, wdw, bdw, out, 0); // idx 2
    k_conv<<<dim3(2, NC, NB), dim3(16, 8)>>>(x, wdw, bdw, out, 2); // idx 3 <- profiled
    k_cov<<<dim3(16, NB), 256>>>(out, w1d, 1);                     // idx 4
    k_att<<<NB, 64>>>(w1d, b1d);                                   // idx 5
    k_scale<<<32768, 256>>>(out);                                  // idx 6
}

// round 15
// speedup vs baseline: 1.0427x; 1.0427x over previous
#include <cuda_runtime.h>
#include <cstdint>

#define NPIX 16384   // 128*128
#define NC   64
#define NB   32

// Scratch (device globals; no allocation allowed).
// g_stats layout: which*4096 + { S: [0..2047] (b*64+c), T: [2048..4095] }
__device__ float g_stats[8192];
__device__ float g_att[2048];
__device__ float g_g1[NB * NPIX];   // g1[b][n] = sum_c w1d[c] * x[b,c,n]  (2 MB)

// ---------------- packed f32x2 helpers ----------------
static __device__ __forceinline__ unsigned long long pk2(float a, float b) {
    unsigned long long r;
    asm("mov.b64 %0, {%1, %2};" : "=l"(r) : "f"(a), "f"(b));
    return r;
}
static __device__ __forceinline__ void ffma2(unsigned long long& d,
                                             unsigned long long a,
                                             unsigned long long b) {
    asm("fma.rn.f32x2 %0, %1, %2, %0;" : "+l"(d) : "l"(a), "l"(b));
}
static __device__ __forceinline__ float2 unpk2(unsigned long long v) {
    float2 f;
    asm("mov.b64 {%0, %1}, %2;" : "=f"(f.x), "=f"(f.y) : "l"(v));
    return f;
}
// (hi(a), lo(b)) -> packed pair. Register-only; ptxas coalesces reg-pair moves.
static __device__ __forceinline__ unsigned long long mix(unsigned long long a,
                                                          unsigned long long b) {
    unsigned long long r;
    asm("{\n\t.reg .b32 x,y,z,w;\n\t"
        "mov.b64 {x,y}, %1;\n\t"
        "mov.b64 {z,w}, %2;\n\t"
        "mov.b64 %0, {y,z};\n\t}"
        : "=l"(r) : "l"(a), "l"(b));
    return r;
}
// Forced 128-bit shared load: ptxas cannot split ld.shared.v2.u64.
static __device__ __forceinline__ void lds_v2u64(unsigned long long& lo,
                                                 unsigned long long& hi,
                                                 uint32_t saddr) {
    asm volatile("ld.shared.v2.u64 {%0, %1}, [%2];"
                 : "=l"(lo), "=l"(hi) : "r"(saddr));
}
static __device__ __forceinline__ unsigned long long lds_u64(uint32_t saddr) {
    unsigned long long v;
    asm volatile("ld.shared.u64 %0, [%1];" : "=l"(v) : "r"(saddr));
    return v;
}

// ---------------- g1 = sum_c w1d[c] * x[b,c,:]  (half the batches) ----------
// grid (16, 16), block 256. b = b_off + blockIdx.y.
// Blocks with blockIdx.x==0 zero this half's share of g_stats (all 8192 words
// covered exactly once across the two launches).
__global__ void k_gx(const float* __restrict__ x,
                     const float* __restrict__ w1d, int b_off) {
    __shared__ float ws[64];
    const int b = b_off + blockIdx.y, tx = threadIdx.x;
    if (blockIdx.x == 0) {
        g_stats[b * 256 + tx] = 0.f;   // b in 0..31
    }
    if (tx < 64) ws[tx] = w1d[tx];
    __syncthreads();

    const float* xb = x + (size_t)b * NC * NPIX + (size_t)blockIdx.x * 1024;
    float4 acc = make_float4(0.f, 0.f, 0.f, 0.f);
#pragma unroll 8
    for (int c = 0; c < 64; c++) {
        float4 v = *(const float4*)(xb + (size_t)c * NPIX + tx * 4);
        float  w = ws[c];
        acc.x += w * v.x; acc.y += w * v.y;
        acc.z += w * v.z; acc.w += w * v.w;
    }
    *(float4*)(g_g1 + (size_t)b * NPIX + blockIdx.x * 1024 + tx * 4) = acc;
}

// ---------------- covariance-projection stats (R2-proven version) ----------
// grid (16, NB), block 256. Each block owns one 1024-pixel slab of one batch.
__global__ void k_cov(const float* __restrict__ x,
                      const float* __restrict__ w1d, int which) {
    __shared__ __align__(16) float g[1024];
    __shared__ float ws[64];
    const int b  = blockIdx.y;
    const int tx = threadIdx.x;
    if (tx < 64) ws[tx] = w1d[tx];
    __syncthreads();

    const float* xb = x + (size_t)b * NC * NPIX + (size_t)blockIdx.x * 1024;

    // Phase A: gRaw over this slab
    float4 acc = make_float4(0.f, 0.f, 0.f, 0.f);
#pragma unroll 8
    for (int c = 0; c < 64; c++) {
        float4 v = *(const float4*)(xb + (size_t)c * NPIX + tx * 4);
        float  w = ws[c];
        acc.x += w * v.x; acc.y += w * v.y;
        acc.z += w * v.z; acc.w += w * v.w;
    }
    *(float4*)(g + tx * 4) = acc;
    __syncthreads();

    // Phase B: per-channel T += x*g, S += x
    const int warp = tx >> 5, lane = tx & 31;
    float* base = g_stats + which * 4096;
    const float4* gp = (const float4*)g;
    for (int j = 0; j < 8; j++) {
        int c = warp * 8 + j;
        const float4* xc = (const float4*)(xb + (size_t)c * NPIX);
        float t = 0.f, s = 0.f;
#pragma unroll
        for (int it = 0; it < 8; it++) {
            float4 v  = xc[lane + it * 32];
            float4 gg = gp[lane + it * 32];
            t += v.x * gg.x + v.y * gg.y + v.z * gg.z + v.w * gg.w;
            s += v.x + v.y + v.z + v.w;
        }
#pragma unroll
        for (int o = 16; o > 0; o >>= 1) {
            t += __shfl_xor_sync(0xffffffffu, t, o);
            s += __shfl_xor_sync(0xffffffffu, s, o);
        }
        if (lane == 0) {
            atomicAdd(base +        b * 64 + c, s);
            atomicAdd(base + 2048 + b * 64 + c, t);
        }
    }
}

// ---------------- 9x9 depthwise conv (pad 4), half the tile rows -----------
// grid (4, NC, NB): tileY = ty_off + blockIdx.x, channel, batch. block (32, 4).
// Output tile 128 wide x 16 high; per-thread 4 contiguous cols x 4 rows.
// Inputs: 3 forced LDS.128 per row fetch ep[0..5] (lane stride 16B -> 100%
// crossbar efficiency); the 5 odd pairs are register-mixed (no shadow tile).
// Fused epilogue: S1 = sum(x), T1 = sum(x * g1) over the tile's output region.
__global__ void __launch_bounds__(128)
k_conv(const float* __restrict__ x,
       const float* __restrict__ wdw,
       const float* __restrict__ bdw,
       float* __restrict__ y, int ty_off) {
    __shared__ __align__(16) float tile[24][136];
    __shared__ __align__(16) unsigned long long wd2[90];  // 9 rows x 10 pairs
    __shared__ float sred[4], tred[4];

    const int tileY = ty_off + blockIdx.x, c = blockIdx.y, b = blockIdx.z;
    const int tx = threadIdx.x, ty = threadIdx.y;     // tx 0..31, ty 0..3
    const int tid = ty * 32 + tx;
    const float* xp = x + (size_t)(b * NC + c) * NPIX;
    const int y0 = tileY * 16;

    if (tid < 81) {
        float w = wdw[c * 81 + tid];
        wd2[(tid / 9) * 10 + (tid % 9)] = pk2(w, w);
    }
    // Tile load: interior as float4, halos zeroed.
    // tile row r = input row y0-4+r; tile cols 4..131 = input cols 0..127.
#pragma unroll
    for (int i = tid; i < 768; i += 128) {            // 24 rows x 32 float4
        int r = i >> 5, k = i & 31;
        int gy = y0 - 4 + r;
        float4 v = make_float4(0.f, 0.f, 0.f, 0.f);
        if (gy >= 0 && gy < 128)
            v = *(const float4*)(xp + gy * 128 + k * 4);
        *(float4*)(&tile[r][4 + k * 4]) = v;
    }
    if (tid < 48) {                                   // zero left/right halo
        int r = tid >> 1;
        *(float4*)(&tile[r][(tid & 1) ? 132 : 0]) =
            make_float4(0.f, 0.f, 0.f, 0.f);
    }
    __syncthreads();

    const float bias = bdw[c];
    const unsigned long long bb = pk2(bias, bias);
    unsigned long long acc[4][2];                     // 4 rows x 2 pairs
#pragma unroll
    for (int oy = 0; oy < 4; oy++) { acc[oy][0] = bb; acc[oy][1] = bb; }

    const int ox    = tx * 4;   // output cols ox..ox+3; window = tile cols ox..
    const int rbase = ty * 4;   // smem row of (first output row - 4)

    const uint32_t tb = (uint32_t)__cvta_generic_to_shared(&tile[rbase][0])
                        + (uint32_t)(ox * 4);         // byte 16*tx, 16B aligned
    const uint32_t wb = (uint32_t)__cvta_generic_to_shared(wd2);
    const uint32_t ROWB = 136 * 4;                    // 544 bytes per row

#pragma unroll
    for (int iy = 0; iy < 12; iy++) {
        const uint32_t ea = tb + iy * ROWB;
        unsigned long long ep[6];
        lds_v2u64(ep[0], ep[1], ea);
        lds_v2u64(ep[2], ep[3], ea + 16);
        lds_v2u64(ep[4], ep[5], ea + 32);
        unsigned long long op[5];
#pragma unroll
        for (int j = 0; j < 5; j++) op[j] = mix(ep[j], ep[j + 1]);

#pragma unroll
        for (int oy = 0; oy < 4; oy++) {
            const int ky = iy - oy;           // compile-time after unroll
            if (ky >= 0 && ky <= 8) {
                const uint32_t wa = wb + ky * 80;
                unsigned long long w0, w1, w2, w3, w4, w5, w6, w7, w8;
                lds_v2u64(w0, w1, wa);
                lds_v2u64(w2, w3, wa + 16);
                lds_v2u64(w4, w5, wa + 32);
                lds_v2u64(w6, w7, wa + 48);
                w8 = lds_u64(wa + 64);
                // pair P0 = output cols (ox, ox+1)
                ffma2(acc[oy][0], ep[0], w0);
                ffma2(acc[oy][0], op[0], w1);
                ffma2(acc[oy][0], ep[1], w2);
                ffma2(acc[oy][0], op[1], w3);
                ffma2(acc[oy][0], ep[2], w4);
                ffma2(acc[oy][0], op[2], w5);
                ffma2(acc[oy][0], ep[3], w6);
                ffma2(acc[oy][0], op[3], w7);
                ffma2(acc[oy][0], ep[4], w8);
                // pair P1 = output cols (ox+2, ox+3)
                ffma2(acc[oy][1], ep[1], w0);
                ffma2(acc[oy][1], op[1], w1);
                ffma2(acc[oy][1], ep[2], w2);
                ffma2(acc[oy][1], op[2], w3);
                ffma2(acc[oy][1], ep[3], w4);
                ffma2(acc[oy][1], op[3], w5);
                ffma2(acc[oy][1], ep[4], w6);
                ffma2(acc[oy][1], op[4], w7);
                ffma2(acc[oy][1], ep[5], w8);
            }
        }
    }

    float* yp = y + (size_t)(b * NC + c) * NPIX;
#pragma unroll
    for (int oy = 0; oy < 4; oy++) {
        float2 lo = unpk2(acc[oy][0]);
        float2 hi = unpk2(acc[oy][1]);
        *(float4*)(yp + (y0 + rbase + oy) * 128 + ox) =
            make_float4(lo.x, lo.y, hi.x, hi.y);
    }

    // ---- fused cov(x) stats: S1 = sum(x), T1 = sum(x * g1) over this tile ----
    const float* g1b = g_g1 + (size_t)b * NPIX;
    float s = 0.f, t = 0.f;
#pragma unroll
    for (int oy = 0; oy < 4; oy++) {
        float4 xv = *(const float4*)(&tile[4 + rbase + oy][4 + ox]);
        float4 gg = __ldg((const float4*)(g1b + (y0 + rbase + oy) * 128 + ox));
        t += xv.x * gg.x + xv.y * gg.y + xv.z * gg.z + xv.w * gg.w;
        s += xv.x + xv.y + xv.z + xv.w;
    }
#pragma unroll
    for (int off = 16; off > 0; off >>= 1) {
        t += __shfl_xor_sync(0xffffffffu, t, off);
        s += __shfl_xor_sync(0xffffffffu, s, off);
    }
    if (tx == 0) { sred[ty] = s; tred[ty] = t; }
    __syncthreads();
    if (tid == 0) {
        float ss = sred[0] + sred[1] + sred[2] + sred[3];
        float tt = tred[0] + tred[1] + tred[2] + tred[3];
        atomicAdd(g_stats +        b * 64 + c, ss);
        atomicAdd(g_stats + 2048 + b * 64 + c, tt);
    }
}

// ---------------- per-batch attention scores ----------------
__device__ __forceinline__ float blk_reduce(float v, float* red, int t, bool ismax) {
    red[t] = v;
    __syncthreads();
#pragma unroll
    for (int s = 32; s > 0; s >>= 1) {
        if (t < s) red[t] = ismax ? fmaxf(red[t], red[t + s]) : red[t] + red[t + s];
        __syncthreads();
    }
    float r = red[0];
    __syncthreads();
    return r;
}

__global__ void k_att(const float* __restrict__ w1d, const float* __restrict__ b1d) {
    __shared__ float red[64];
    const int b = blockIdx.x, t = threadIdx.x;
    const float invN  = 1.f / 16384.f;
    const float invN1 = 1.f / 16383.f;

    float S1 = g_stats[          b * 64 + t];
    float T1 = g_stats[2048 +    b * 64 + t];
    float S2 = g_stats[4096 +    b * 64 + t];
    float T2 = g_stats[6144 +    b * 64 + t];
    float w  = w1d[t];

    float Sg1 = blk_reduce(w * S1, red, t, false);
    float Sg2 = blk_reduce(w * S2, red, t, false);
    float bb  = b1d[0];
    float c1  = (T1 - Sg1 * S1 * invN) * invN1 + bb;
    float c2  = (T2 - Sg2 * S2 * invN) * invN1 + bb;

    float d  = c2 - c1;
    float m  = blk_reduce(d, red, t, true);
    float e  = expf(d - m);
    float se = blk_reduce(e, red, t, false);
    float raise = e / se;
    float att = 1.f / (1.f + expf(-c2 * (1.f + raise)));
    g_att[b * 64 + t] = att;
}

// ---------------- in-place scaling of y by att ----------------
// grid 32768, block 256; each block = 1024 floats inside one (b,c) channel.
__global__ void k_scale(float* __restrict__ y) {
    const float a = g_att[blockIdx.x >> 4];
    float4* p = (float4*)y;
    int i = blockIdx.x * 256 + threadIdx.x;
    float4 v = p[i];
    v.x *= a; v.y *= a; v.z *= a; v.w *= a;
    p[i] = v;
}

extern "C" void kernel_launch(void* const* d_in, const int* in_sizes, int n_in,
                              void* d_out, int out_size) {
    const float* x   = (const float*)d_in[0];
    const float* w1d = (const float*)d_in[1];
    const float* b1d = (const float*)d_in[2];
    const float* wdw = (const float*)d_in[3];
    const float* bdw = (const float*)d_in[4];
    float* out = (float*)d_out;

    // Launch order chosen so absolute launch index 3 (the ncu-captured slot)
    // is a k_conv half.
    k_gx<<<dim3(16, 16), 256>>>(x, w1d, 0);                        // idx 0
    k_gx<<<dim3(16, 16), 256>>>(x, w1d, 16);                       // idx 1
    k_conv<<<dim3(4, NC, NB), dim3(32, 4)>>>(x, wdw, bdw, out, 0); // idx 2
    k_conv<<<dim3(4, NC, NB), dim3(32, 4)>>>(x, wdw, bdw, out, 4); // idx 3 <- profiled
    k_cov<<<dim3(16, NB), 256>>>(out, w1d, 1);                     // idx 4
    k_att<<<NB, 64>>>(w1d, b1d);                                   // idx 5
    k_scale<<<32768, 256>>>(out);                                  // idx 6
}